// round 7
// baseline (speedup 1.0000x reference)
#include <cuda_runtime.h>
#include <cuda_bf16.h>

typedef unsigned long long ULL;

// Problem constants (fixed by setup_inputs)
#define IH 2160
#define IW 3840
#define HW (IH * IW)
#define KS 25
#define PADK 12
#define LH (IH + 22)
#define LW (IW + 22)
#define L3 (3 * LH * LW)

// Blur tiling: 32 cols x 64 rows per block; each thread covers rows (lane, lane+32)
#define TILE_X 32
#define TILE_Y 64
#define SROWS 88           // 64 + 24 halo       (type A: ch0/ch1 packed)
#define SPROWS 56          // pair rows          (type B: ch2 rows (r, r+32))
#define SCOLS 56           // 32 + 24 halo
#define SSTRIDE 57
#define BLK_THREADS 128    // 4 warps x 8 cols, lane = row index

#define RING 10            // window ring slots (use->refill distance ~3 iters)
#define WRING 6            // weight ring slots (use->refill distance ~6 iters)

#define SPK_ELEMS (SROWS * SSTRIDE)                 // float2 (type A tile, superset)
#define SWT_ELEMS (KS * KS)                         // float2 duplicated weights
#define SMEM_BYTES ((SPK_ELEMS + SWT_ELEMS) * 8)    // 45,128 B

// Laplacian
#define LAP_ROWS (3 * LH)            // 6546
#define LAP_THREADS 256
#define LAP_VCHUNKS 958              // vector chunks: cc0 = 4 + 4c
__device__ float g_partials[LAP_ROWS];

__device__ __forceinline__ int clampi(int v, int lo, int hi) {
    return min(max(v, lo), hi);
}

// ---------------------------------------------------------------------------
// Kernel 1: 25x25 depthwise blur, edge-replicate pad, + noise. All FFMA2.
// gridDim.z = 2:
//   z==0 (type A): ch0,ch1 packed f32x2; thread computes rows y0=lane, y1=lane+32.
//   z==1 (type B): ch2 rows (y0,y1) packed f32x2 via pair tile.
// 10-slot window rings + 6-slot weight ring: every LDS has >=3 iterations of
// slack before first use, hiding the 29-cyc LDS latency inside each warp.
// ---------------------------------------------------------------------------
__global__ void __launch_bounds__(BLK_THREADS)
blur_kernel(const float* __restrict__ img,
            const float* __restrict__ noise,
            const float* __restrict__ g,
            float* __restrict__ out)
{
    extern __shared__ float2 smem[];
    float2* tile = smem;                 // A: [88 x 57]  B: [56 x 57] (prefix)
    float2* swt2 = smem + SPK_ELEMS;     // duplicated weights [625]

    const int tx0 = blockIdx.x * TILE_X;
    const int ty0 = blockIdx.y * TILE_Y;
    const int tid = threadIdx.x;

    // duplicated weights
    for (int i = tid; i < SWT_ELEMS; i += BLK_THREADS) {
        float w = g[i];
        swt2[i] = make_float2(w, w);
    }

    const int lane = tid & 31;      // row index within tile (y0 = ty0+lane)
    const int wid  = tid >> 5;      // x-group (0..3)
    const int xb   = wid * 8;       // column base within tile
    const int x    = tx0 + xb;

    if (blockIdx.z == 0) {
        // ---------------- Type A: channels 0,1 ----------------
        for (int i = tid; i < SROWS * SCOLS; i += BLK_THREADS) {
            int r = i / SCOLS, c = i % SCOLS;
            int gy = clampi(ty0 - PADK + r, 0, IH - 1);
            int gx = clampi(tx0 - PADK + c, 0, IW - 1);
            int gi = gy * IW + gx;
            tile[r * SSTRIDE + c] = make_float2(img[gi], img[HW + gi]);
        }
        __syncthreads();

        ULL acc0[8], acc1[8];
#pragma unroll
        for (int j = 0; j < 8; j++) { acc0[j] = 0ull; acc1[j] = 0ull; }

#pragma unroll 1
        for (int ky = 0; ky < KS; ++ky) {
            const ULL* r0 = reinterpret_cast<const ULL*>(tile + (lane + ky) * SSTRIDE + xb);
            const ULL* r1 = reinterpret_cast<const ULL*>(tile + (lane + 32 + ky) * SSTRIDE + xb);
            const ULL* wp = reinterpret_cast<const ULL*>(swt2 + ky * KS);

            ULL a[RING], b[RING], wr[WRING];
#pragma unroll
            for (int i = 0; i < RING; i++) { a[i] = r0[i]; b[i] = r1[i]; }
#pragma unroll
            for (int i = 0; i < WRING; i++) wr[i] = wp[i];

#pragma unroll
            for (int kx = 0; kx < KS; ++kx) {
#pragma unroll
                for (int j = 0; j < 8; j++) {
                    const int s = (kx + j) % RING;      // compile-time
                    const int w = kx % WRING;
                    asm("fma.rn.f32x2 %0, %1, %2, %0;" : "+l"(acc0[j]) : "l"(a[s]), "l"(wr[w]));
                    asm("fma.rn.f32x2 %0, %1, %2, %0;" : "+l"(acc1[j]) : "l"(b[s]), "l"(wr[w]));
                }
                if (kx < KS - WRING)
                    wr[kx % WRING] = wp[kx + WRING];     // used at kx+WRING
                if (kx < KS - 3) {                       // need cols up to 31
                    a[kx % RING] = r0[RING + kx];        // used at kx+3 earliest
                    b[kx % RING] = r1[RING + kx];
                }
            }
        }

        {   // row y0 (always valid)
            const int base = (ty0 + lane) * IW + x;
            float4 n0 = *reinterpret_cast<const float4*>(noise + base);
            float4 n1 = *reinterpret_cast<const float4*>(noise + base + 4);
            float v0[8], v1[8];
#pragma unroll
            for (int j = 0; j < 8; j++) {
                float2 f = *reinterpret_cast<float2*>(&acc0[j]);
                v0[j] = f.x; v1[j] = f.y;
            }
            *reinterpret_cast<float4*>(out + 0 * HW + base) =
                make_float4(v0[0] + n0.x, v0[1] + n0.y, v0[2] + n0.z, v0[3] + n0.w);
            *reinterpret_cast<float4*>(out + 0 * HW + base + 4) =
                make_float4(v0[4] + n1.x, v0[5] + n1.y, v0[6] + n1.z, v0[7] + n1.w);
            *reinterpret_cast<float4*>(out + 1 * HW + base) =
                make_float4(v1[0] + n0.x, v1[1] + n0.y, v1[2] + n0.z, v1[3] + n0.w);
            *reinterpret_cast<float4*>(out + 1 * HW + base + 4) =
                make_float4(v1[4] + n1.x, v1[5] + n1.y, v1[6] + n1.z, v1[7] + n1.w);
        }
        const int y1 = ty0 + lane + 32;
        if (y1 < IH) {
            const int base = y1 * IW + x;
            float4 n0 = *reinterpret_cast<const float4*>(noise + base);
            float4 n1 = *reinterpret_cast<const float4*>(noise + base + 4);
            float v0[8], v1[8];
#pragma unroll
            for (int j = 0; j < 8; j++) {
                float2 f = *reinterpret_cast<float2*>(&acc1[j]);
                v0[j] = f.x; v1[j] = f.y;
            }
            *reinterpret_cast<float4*>(out + 0 * HW + base) =
                make_float4(v0[0] + n0.x, v0[1] + n0.y, v0[2] + n0.z, v0[3] + n0.w);
            *reinterpret_cast<float4*>(out + 0 * HW + base + 4) =
                make_float4(v0[4] + n1.x, v0[5] + n1.y, v0[6] + n1.z, v0[7] + n1.w);
            *reinterpret_cast<float4*>(out + 1 * HW + base) =
                make_float4(v1[0] + n0.x, v1[1] + n0.y, v1[2] + n0.z, v1[3] + n0.w);
            *reinterpret_cast<float4*>(out + 1 * HW + base + 4) =
                make_float4(v1[4] + n1.x, v1[5] + n1.y, v1[6] + n1.z, v1[7] + n1.w);
        }
    } else {
        // ---------------- Type B: channel 2, row pairs ----------------
        const float* img2 = img + 2 * HW;
        for (int i = tid; i < SPROWS * SCOLS; i += BLK_THREADS) {
            int r = i / SCOLS, c = i % SCOLS;
            int gx  = clampi(tx0 - PADK + c, 0, IW - 1);
            int gy0 = clampi(ty0 - PADK + r,      0, IH - 1);
            int gy1 = clampi(ty0 - PADK + r + 32, 0, IH - 1);
            tile[r * SSTRIDE + c] = make_float2(img2[gy0 * IW + gx], img2[gy1 * IW + gx]);
        }
        __syncthreads();

        ULL acc2[8];
#pragma unroll
        for (int j = 0; j < 8; j++) acc2[j] = 0ull;

#pragma unroll 1
        for (int ky = 0; ky < KS; ++ky) {
            const ULL* p2 = reinterpret_cast<const ULL*>(tile + (lane + ky) * SSTRIDE + xb);
            const ULL* wp = reinterpret_cast<const ULL*>(swt2 + ky * KS);

            ULL c[RING], wr[WRING];
#pragma unroll
            for (int i = 0; i < RING; i++) c[i] = p2[i];
#pragma unroll
            for (int i = 0; i < WRING; i++) wr[i] = wp[i];

#pragma unroll
            for (int kx = 0; kx < KS; ++kx) {
#pragma unroll
                for (int j = 0; j < 8; j++) {
                    const int s = (kx + j) % RING;
                    asm("fma.rn.f32x2 %0, %1, %2, %0;"
                        : "+l"(acc2[j]) : "l"(c[s]), "l"(wr[kx % WRING]));
                }
                if (kx < KS - WRING)
                    wr[kx % WRING] = wp[kx + WRING];
                if (kx < KS - 3)
                    c[kx % RING] = p2[RING + kx];
            }
        }

        {   // row y0
            const int base = (ty0 + lane) * IW + x;
            float4 n0 = *reinterpret_cast<const float4*>(noise + base);
            float4 n1 = *reinterpret_cast<const float4*>(noise + base + 4);
            float v[8];
#pragma unroll
            for (int j = 0; j < 8; j++) v[j] = reinterpret_cast<float2*>(&acc2[j])->x;
            *reinterpret_cast<float4*>(out + 2 * HW + base) =
                make_float4(v[0] + n0.x, v[1] + n0.y, v[2] + n0.z, v[3] + n0.w);
            *reinterpret_cast<float4*>(out + 2 * HW + base + 4) =
                make_float4(v[4] + n1.x, v[5] + n1.y, v[6] + n1.z, v[7] + n1.w);
        }
        const int y1 = ty0 + lane + 32;
        if (y1 < IH) {
            const int base = y1 * IW + x;
            float4 n0 = *reinterpret_cast<const float4*>(noise + base);
            float4 n1 = *reinterpret_cast<const float4*>(noise + base + 4);
            float v[8];
#pragma unroll
            for (int j = 0; j < 8; j++) v[j] = reinterpret_cast<float2*>(&acc2[j])->y;
            *reinterpret_cast<float4*>(out + 2 * HW + base) =
                make_float4(v[0] + n0.x, v[1] + n0.y, v[2] + n0.z, v[3] + n0.w);
            *reinterpret_cast<float4*>(out + 2 * HW + base + 4) =
                make_float4(v[4] + n1.x, v[5] + n1.y, v[6] + n1.z, v[7] + n1.w);
        }
    }
}

// ---------------------------------------------------------------------------
// Kernel 2: Laplacian (3x3, pad=12 replicate), squared, per-row partial sums.
// ---------------------------------------------------------------------------
__global__ void __launch_bounds__(LAP_THREADS)
lap_kernel(const float* __restrict__ img)
{
    const int row = blockIdx.x;          // 0 .. LAP_ROWS-1
    const int ch  = row / LH;
    const int oy  = row - ch * LH;
    const float* p = img + ch * HW;

    const int ru = clampi(oy - 12, 0, IH - 1);
    const int rc = clampi(oy - 11, 0, IH - 1);
    const int rd = clampi(oy - 10, 0, IH - 1);
    const float* __restrict__ pu = p + ru * IW;
    const float* __restrict__ pc = p + rc * IW;
    const float* __restrict__ pd = p + rd * IW;

    float acc = 0.0f;

    // vector interior: cc0 = 4 + 4c (16B aligned)
    for (int c = threadIdx.x; c < LAP_VCHUNKS; c += LAP_THREADS) {
        int cc0 = 4 + 4 * c;
        float4 u = *reinterpret_cast<const float4*>(pu + cc0);
        float4 m = *reinterpret_cast<const float4*>(pc + cc0);
        float4 d = *reinterpret_cast<const float4*>(pd + cc0);
        float l = pc[cc0 - 1];
        float r = pc[cc0 + 4];
        float v0 = 4.0f * m.x - u.x - d.x - l   - m.y;
        float v1 = 4.0f * m.y - u.y - d.y - m.x - m.z;
        float v2 = 4.0f * m.z - u.z - d.z - m.y - m.w;
        float v3 = 4.0f * m.w - u.w - d.w - m.z - r;
        acc = fmaf(v0, v0, acc);
        acc = fmaf(v1, v1, acc);
        acc = fmaf(v2, v2, acc);
        acc = fmaf(v3, v3, acc);
    }

    // scalar edges: ox in [0,14] and [3847, 3861]
    if (threadIdx.x < 30) {
        int t = threadIdx.x;
        int ox = (t < 15) ? t : (3832 + t);
        int cl = clampi(ox - 12, 0, IW - 1);
        int cc = clampi(ox - 11, 0, IW - 1);
        int cr = clampi(ox - 10, 0, IW - 1);
        float v = 4.0f * pc[cc] - pu[cc] - pd[cc] - pc[cl] - pc[cr];
        acc = fmaf(v, v, acc);
    }

    __shared__ float sbuf[LAP_THREADS];
    sbuf[threadIdx.x] = acc;
    __syncthreads();
#pragma unroll
    for (int s = LAP_THREADS / 2; s > 0; s >>= 1) {
        if (threadIdx.x < s) sbuf[threadIdx.x] += sbuf[threadIdx.x + s];
        __syncthreads();
    }
    if (threadIdx.x == 0) g_partials[row] = sbuf[0];
}

// ---------------------------------------------------------------------------
// Kernel 3: final deterministic reduction in double -> mean scalar.
// ---------------------------------------------------------------------------
__global__ void __launch_bounds__(256)
reduce_kernel(float* __restrict__ out_scalar)
{
    __shared__ double sd[256];
    double s = 0.0;
    for (int i = threadIdx.x; i < LAP_ROWS; i += 256) s += (double)g_partials[i];
    sd[threadIdx.x] = s;
    __syncthreads();
#pragma unroll
    for (int k = 128; k > 0; k >>= 1) {
        if (threadIdx.x < k) sd[threadIdx.x] += sd[threadIdx.x + k];
        __syncthreads();
    }
    if (threadIdx.x == 0)
        out_scalar[0] = (float)(sd[0] / (double)L3);
}

extern "C" void kernel_launch(void* const* d_in, const int* in_sizes, int n_in,
                              void* d_out, int out_size)
{
    const float* img   = (const float*)d_in[0];  // (1,3,2160,3840)
    const float* noise = (const float*)d_in[1];  // (1,1,2160,3840)
    const float* g     = (const float*)d_in[2];  // (25,25)
    float* out = (float*)d_out;                  // [3*H*W conv output, 1 scalar]

    static bool attr_set = false;
    if (!attr_set) {
        cudaFuncSetAttribute(blur_kernel,
                             cudaFuncAttributeMaxDynamicSharedMemorySize, SMEM_BYTES);
        attr_set = true;
    }

    dim3 gridB(IW / TILE_X, (IH + TILE_Y - 1) / TILE_Y, 2);   // 120 x 34 x 2
    blur_kernel<<<gridB, BLK_THREADS, SMEM_BYTES>>>(img, noise, g, out);

    lap_kernel<<<LAP_ROWS, LAP_THREADS>>>(img);
    reduce_kernel<<<1, 256>>>(out + (out_size - 1));
}

// round 9
// speedup vs baseline: 1.1114x; 1.1114x over previous
#include <cuda_runtime.h>
#include <cuda_bf16.h>

// Problem constants (fixed by setup_inputs)
#define IH 2160
#define IW 3840
#define HW (IH * IW)
#define KS 25
#define PADK 12
#define LH (IH + 22)
#define LW (IW + 22)
#define L3 (3 * LH * LW)

// Blur tiling: 32x32 outputs per block, 128 threads (4 warps x 8 cols, lane = row)
#define TILE 32
#define SROWS 56
#define SCOLS 56
#define SSTRIDE 57
#define BLK_THREADS 128
#define RING 10            // rotating window slots (refill->use distance >= 3 iters)

// Weights live in constant memory -> LDCU -> uniform-register FFMA operand (rt=1)
__constant__ float c_w[KS * KS];

// Laplacian
#define LAP_ROWS (3 * LH)            // 6546
#define LAP_THREADS 256
#define LAP_VCHUNKS 958              // vector chunks: cc0 = 4 + 4c
__device__ float g_partials[LAP_ROWS];

__device__ __forceinline__ int clampi(int v, int lo, int hi) {
    return min(max(v, lo), hi);
}

// ---------------------------------------------------------------------------
// Kernel 1: 25x25 depthwise blur, edge-replicate pad, + noise.
// All-scalar FFMA with constant-memory weights: FFMA R, R, UR, R reads only
// 2 GPRs -> rt=1 per SMSP (vs rt=3 for 3-pair FFMA2). Weight fetch uses the
// uniform-const port, off the LDS crossbar.
// NOTE: 2160/32 = 67.5 -> last block row is half-tall; epilogue guarded.
// ---------------------------------------------------------------------------
__global__ void __launch_bounds__(BLK_THREADS)
blur_kernel(const float* __restrict__ img,
            const float* __restrict__ noise,
            float* __restrict__ out)
{
    __shared__ float2 s01[SROWS * SSTRIDE];  // channels 0,1 packed
    __shared__ float  s2 [SROWS * SSTRIDE];  // channel 2

    const int tx0 = blockIdx.x * TILE;
    const int ty0 = blockIdx.y * TILE;
    const int tid = threadIdx.x;

    // load input tile with edge clamp (3 channels)
    for (int i = tid; i < SROWS * SCOLS; i += BLK_THREADS) {
        int r = i / SCOLS, c = i % SCOLS;
        int gy = clampi(ty0 - PADK + r, 0, IH - 1);
        int gx = clampi(tx0 - PADK + c, 0, IW - 1);
        int gi = gy * IW + gx;
        s01[r * SSTRIDE + c] = make_float2(img[gi], img[HW + gi]);
        s2 [r * SSTRIDE + c] = img[2 * HW + gi];
    }
    __syncthreads();

    const int lane = tid & 31;      // output row within tile
    const int wid  = tid >> 5;      // x-group (0..3)
    const int xb   = wid * 8;       // column base within tile

    float acc0[8], acc1[8], acc2[8];
#pragma unroll
    for (int j = 0; j < 8; j++) { acc0[j] = 0.0f; acc1[j] = 0.0f; acc2[j] = 0.0f; }

#pragma unroll 1
    for (int ky = 0; ky < KS; ++ky) {
        const float2* rowp = s01 + (lane + ky) * SSTRIDE + xb;
        const float*  row2 = s2  + (lane + ky) * SSTRIDE + xb;
        const int wbase = ky * KS;

        // prime rotating windows (cols xb+0 .. xb+9)
        float2 a[RING];
        float  c2[RING];
#pragma unroll
        for (int i = 0; i < RING; i++) { a[i] = rowp[i]; c2[i] = row2[i]; }

#pragma unroll
        for (int kx = 0; kx < KS; ++kx) {
            const float wv = c_w[wbase + kx];   // LDCU -> UR, uniform port
#pragma unroll
            for (int j = 0; j < 8; j++) {
                const int s = (kx + j) % RING;  // compile-time slot
                acc0[j] = fmaf(a[s].x, wv, acc0[j]);
                acc1[j] = fmaf(a[s].y, wv, acc1[j]);
                acc2[j] = fmaf(c2[s],  wv, acc2[j]);
            }
            if (kx < KS - 3) {                  // cols 10..31; used >=3 iters later
                a [kx % RING] = rowp[RING + kx];
                c2[kx % RING] = row2[RING + kx];
            }
        }
    }

    const int y = ty0 + lane;
    if (y < IH) {                               // last block row is half-tall
        const int x = tx0 + xb;
        const int base = y * IW + x;
        float4 n0 = *reinterpret_cast<const float4*>(noise + base);
        float4 n1 = *reinterpret_cast<const float4*>(noise + base + 4);

        *reinterpret_cast<float4*>(out + 0 * HW + base) =
            make_float4(acc0[0] + n0.x, acc0[1] + n0.y, acc0[2] + n0.z, acc0[3] + n0.w);
        *reinterpret_cast<float4*>(out + 0 * HW + base + 4) =
            make_float4(acc0[4] + n1.x, acc0[5] + n1.y, acc0[6] + n1.z, acc0[7] + n1.w);
        *reinterpret_cast<float4*>(out + 1 * HW + base) =
            make_float4(acc1[0] + n0.x, acc1[1] + n0.y, acc1[2] + n0.z, acc1[3] + n0.w);
        *reinterpret_cast<float4*>(out + 1 * HW + base + 4) =
            make_float4(acc1[4] + n1.x, acc1[5] + n1.y, acc1[6] + n1.z, acc1[7] + n1.w);
        *reinterpret_cast<float4*>(out + 2 * HW + base) =
            make_float4(acc2[0] + n0.x, acc2[1] + n0.y, acc2[2] + n0.z, acc2[3] + n0.w);
        *reinterpret_cast<float4*>(out + 2 * HW + base + 4) =
            make_float4(acc2[4] + n1.x, acc2[5] + n1.y, acc2[6] + n1.z, acc2[7] + n1.w);
    }
}

// ---------------------------------------------------------------------------
// Kernel 2: Laplacian (3x3, pad=12 replicate), squared, per-row partial sums.
// ---------------------------------------------------------------------------
__global__ void __launch_bounds__(LAP_THREADS)
lap_kernel(const float* __restrict__ img)
{
    const int row = blockIdx.x;          // 0 .. LAP_ROWS-1
    const int ch  = row / LH;
    const int oy  = row - ch * LH;
    const float* p = img + ch * HW;

    const int ru = clampi(oy - 12, 0, IH - 1);
    const int rc = clampi(oy - 11, 0, IH - 1);
    const int rd = clampi(oy - 10, 0, IH - 1);
    const float* __restrict__ pu = p + ru * IW;
    const float* __restrict__ pc = p + rc * IW;
    const float* __restrict__ pd = p + rd * IW;

    float acc = 0.0f;

    // vector interior: cc0 = 4 + 4c (16B aligned)
    for (int c = threadIdx.x; c < LAP_VCHUNKS; c += LAP_THREADS) {
        int cc0 = 4 + 4 * c;
        float4 u = *reinterpret_cast<const float4*>(pu + cc0);
        float4 m = *reinterpret_cast<const float4*>(pc + cc0);
        float4 d = *reinterpret_cast<const float4*>(pd + cc0);
        float l = pc[cc0 - 1];
        float r = pc[cc0 + 4];
        float v0 = 4.0f * m.x - u.x - d.x - l   - m.y;
        float v1 = 4.0f * m.y - u.y - d.y - m.x - m.z;
        float v2 = 4.0f * m.z - u.z - d.z - m.y - m.w;
        float v3 = 4.0f * m.w - u.w - d.w - m.z - r;
        acc = fmaf(v0, v0, acc);
        acc = fmaf(v1, v1, acc);
        acc = fmaf(v2, v2, acc);
        acc = fmaf(v3, v3, acc);
    }

    // scalar edges: ox in [0,14] and [3847, 3861]
    if (threadIdx.x < 30) {
        int t = threadIdx.x;
        int ox = (t < 15) ? t : (3832 + t);
        int cl = clampi(ox - 12, 0, IW - 1);
        int cc = clampi(ox - 11, 0, IW - 1);
        int cr = clampi(ox - 10, 0, IW - 1);
        float v = 4.0f * pc[cc] - pu[cc] - pd[cc] - pc[cl] - pc[cr];
        acc = fmaf(v, v, acc);
    }

    __shared__ float sbuf[LAP_THREADS];
    sbuf[threadIdx.x] = acc;
    __syncthreads();
#pragma unroll
    for (int s = LAP_THREADS / 2; s > 0; s >>= 1) {
        if (threadIdx.x < s) sbuf[threadIdx.x] += sbuf[threadIdx.x + s];
        __syncthreads();
    }
    if (threadIdx.x == 0) g_partials[row] = sbuf[0];
}

// ---------------------------------------------------------------------------
// Kernel 3: final deterministic reduction in double -> mean scalar.
// ---------------------------------------------------------------------------
__global__ void __launch_bounds__(256)
reduce_kernel(float* __restrict__ out_scalar)
{
    __shared__ double sd[256];
    double s = 0.0;
    for (int i = threadIdx.x; i < LAP_ROWS; i += 256) s += (double)g_partials[i];
    sd[threadIdx.x] = s;
    __syncthreads();
#pragma unroll
    for (int k = 128; k > 0; k >>= 1) {
        if (threadIdx.x < k) sd[threadIdx.x] += sd[threadIdx.x + k];
        __syncthreads();
    }
    if (threadIdx.x == 0)
        out_scalar[0] = (float)(sd[0] / (double)L3);
}

extern "C" void kernel_launch(void* const* d_in, const int* in_sizes, int n_in,
                              void* d_out, int out_size)
{
    const float* img   = (const float*)d_in[0];  // (1,3,2160,3840)
    const float* noise = (const float*)d_in[1];  // (1,1,2160,3840)
    const float* g     = (const float*)d_in[2];  // (25,25)
    float* out = (float*)d_out;                  // [3*H*W conv output, 1 scalar]

    // Weights -> constant bank (async D2D copy; graph-capturable).
    cudaMemcpyToSymbolAsync(c_w, g, KS * KS * sizeof(float), 0,
                            cudaMemcpyDeviceToDevice, 0);

    dim3 gridB(IW / TILE, (IH + TILE - 1) / TILE);   // 120 x 68
    blur_kernel<<<gridB, BLK_THREADS>>>(img, noise, out);

    lap_kernel<<<LAP_ROWS, LAP_THREADS>>>(img);
    reduce_kernel<<<1, 256>>>(out + (out_size - 1));
}

// round 10
// speedup vs baseline: 1.1554x; 1.0396x over previous
#include <cuda_runtime.h>
#include <cuda_bf16.h>

typedef unsigned long long ULL;

// Problem constants (fixed by setup_inputs)
#define IH 2160
#define IW 3840
#define HW (IH * IW)
#define KS 25
#define PADK 12
#define LH (IH + 22)
#define LW (IW + 22)
#define L3 (3 * LH * LW)

// Blur tiling: 32x32 outputs per block, 128 threads (4 warps x 8 cols, lane = row)
#define TILE 32
#define SROWS 56
#define SCOLS 56
#define SSTRIDE 57
#define BLK_THREADS 128
#define RING 10            // rotating window slots (refill->use distance >= 3 iters)

// Weights in constant memory:
//   c_w  : scalar weights  -> UR operand for scalar FFMA (ch2), rt=1
//   c_w2 : duplicated (w,w) pairs -> UR64 operand for fma.rn.f32x2 (ch0/1), rt=2 for 2 FMAs
__constant__ float c_w [KS * KS];
__constant__ ULL   c_w2[KS * KS];
__device__   ULL   g_w2_stage[KS * KS];   // staging for duplicated pairs

// Laplacian
#define LAP_ROWS (3 * LH)            // 6546
#define LAP_THREADS 256
#define LAP_VCHUNKS 958              // vector chunks: cc0 = 4 + 4c
__device__ float g_partials[LAP_ROWS];

__device__ __forceinline__ int clampi(int v, int lo, int hi) {
    return min(max(v, lo), hi);
}

// ---------------------------------------------------------------------------
// Kernel 0: duplicate weights into (w,w) 64-bit pairs (staging for c_w2).
// ---------------------------------------------------------------------------
__global__ void dup_kernel(const float* __restrict__ g)
{
    int i = blockIdx.x * blockDim.x + threadIdx.x;
    if (i < KS * KS) {
        float w = g[i];
        float2 p = make_float2(w, w);
        g_w2_stage[i] = *reinterpret_cast<ULL*>(&p);
    }
}

// ---------------------------------------------------------------------------
// Kernel 1: 25x25 depthwise blur, edge-replicate pad, + noise.
// ch0/ch1: packed f32x2 FFMA with UR64 constant weight pair (2 FMAs / slot).
// ch2:     scalar FFMA with UR constant weight (1 FMA / slot, rt=1).
// fma-pipe cycles unchanged vs all-scalar; issue slots cut ~30%.
// ---------------------------------------------------------------------------
__global__ void __launch_bounds__(BLK_THREADS)
blur_kernel(const float* __restrict__ img,
            const float* __restrict__ noise,
            float* __restrict__ out)
{
    __shared__ float2 s01[SROWS * SSTRIDE];  // channels 0,1 packed
    __shared__ float  s2 [SROWS * SSTRIDE];  // channel 2

    const int tx0 = blockIdx.x * TILE;
    const int ty0 = blockIdx.y * TILE;
    const int tid = threadIdx.x;

    // load input tile with edge clamp (3 channels)
    for (int i = tid; i < SROWS * SCOLS; i += BLK_THREADS) {
        int r = i / SCOLS, c = i % SCOLS;
        int gy = clampi(ty0 - PADK + r, 0, IH - 1);
        int gx = clampi(tx0 - PADK + c, 0, IW - 1);
        int gi = gy * IW + gx;
        s01[r * SSTRIDE + c] = make_float2(img[gi], img[HW + gi]);
        s2 [r * SSTRIDE + c] = img[2 * HW + gi];
    }
    __syncthreads();

    const int lane = tid & 31;      // output row within tile
    const int wid  = tid >> 5;      // x-group (0..3)
    const int xb   = wid * 8;       // column base within tile

    ULL   acc01[8];
    float acc2 [8];
#pragma unroll
    for (int j = 0; j < 8; j++) { acc01[j] = 0ull; acc2[j] = 0.0f; }

#pragma unroll 1
    for (int ky = 0; ky < KS; ++ky) {
        const ULL*   rowp = reinterpret_cast<const ULL*>(s01 + (lane + ky) * SSTRIDE + xb);
        const float* row2 = s2 + (lane + ky) * SSTRIDE + xb;
        const int wbase = ky * KS;

        // prime rotating windows (cols xb+0 .. xb+9)
        ULL   a [RING];
        float c2[RING];
#pragma unroll
        for (int i = 0; i < RING; i++) { a[i] = rowp[i]; c2[i] = row2[i]; }

#pragma unroll
        for (int kx = 0; kx < KS; ++kx) {
            const ULL   ww = c_w2[wbase + kx];  // uniform -> UR64
            const float wv = c_w [wbase + kx];  // uniform -> UR
#pragma unroll
            for (int j = 0; j < 8; j++) {
                const int s = (kx + j) % RING;  // compile-time slot
                asm("fma.rn.f32x2 %0, %1, %2, %0;"
                    : "+l"(acc01[j]) : "l"(a[s]), "l"(ww));
                acc2[j] = fmaf(c2[s], wv, acc2[j]);
            }
            if (kx < KS - 3) {                  // cols 10..31; used >=3 iters later
                a [kx % RING] = rowp[RING + kx];
                c2[kx % RING] = row2[RING + kx];
            }
        }
    }

    const int y = ty0 + lane;
    if (y < IH) {                               // last block row is half-tall
        const int x = tx0 + xb;
        const int base = y * IW + x;
        float4 n0 = *reinterpret_cast<const float4*>(noise + base);
        float4 n1 = *reinterpret_cast<const float4*>(noise + base + 4);

        float v0[8], v1[8];
#pragma unroll
        for (int j = 0; j < 8; j++) {
            float2 f = *reinterpret_cast<float2*>(&acc01[j]);
            v0[j] = f.x; v1[j] = f.y;
        }
        *reinterpret_cast<float4*>(out + 0 * HW + base) =
            make_float4(v0[0] + n0.x, v0[1] + n0.y, v0[2] + n0.z, v0[3] + n0.w);
        *reinterpret_cast<float4*>(out + 0 * HW + base + 4) =
            make_float4(v0[4] + n1.x, v0[5] + n1.y, v0[6] + n1.z, v0[7] + n1.w);
        *reinterpret_cast<float4*>(out + 1 * HW + base) =
            make_float4(v1[0] + n0.x, v1[1] + n0.y, v1[2] + n0.z, v1[3] + n0.w);
        *reinterpret_cast<float4*>(out + 1 * HW + base + 4) =
            make_float4(v1[4] + n1.x, v1[5] + n1.y, v1[6] + n1.z, v1[7] + n1.w);
        *reinterpret_cast<float4*>(out + 2 * HW + base) =
            make_float4(acc2[0] + n0.x, acc2[1] + n0.y, acc2[2] + n0.z, acc2[3] + n0.w);
        *reinterpret_cast<float4*>(out + 2 * HW + base + 4) =
            make_float4(acc2[4] + n1.x, acc2[5] + n1.y, acc2[6] + n1.z, acc2[7] + n1.w);
    }
}

// ---------------------------------------------------------------------------
// Kernel 2: Laplacian (3x3, pad=12 replicate), squared, per-row partial sums.
// ---------------------------------------------------------------------------
__global__ void __launch_bounds__(LAP_THREADS)
lap_kernel(const float* __restrict__ img)
{
    const int row = blockIdx.x;          // 0 .. LAP_ROWS-1
    const int ch  = row / LH;
    const int oy  = row - ch * LH;
    const float* p = img + ch * HW;

    const int ru = clampi(oy - 12, 0, IH - 1);
    const int rc = clampi(oy - 11, 0, IH - 1);
    const int rd = clampi(oy - 10, 0, IH - 1);
    const float* __restrict__ pu = p + ru * IW;
    const float* __restrict__ pc = p + rc * IW;
    const float* __restrict__ pd = p + rd * IW;

    float acc = 0.0f;

    // vector interior: cc0 = 4 + 4c (16B aligned)
    for (int c = threadIdx.x; c < LAP_VCHUNKS; c += LAP_THREADS) {
        int cc0 = 4 + 4 * c;
        float4 u = *reinterpret_cast<const float4*>(pu + cc0);
        float4 m = *reinterpret_cast<const float4*>(pc + cc0);
        float4 d = *reinterpret_cast<const float4*>(pd + cc0);
        float l = pc[cc0 - 1];
        float r = pc[cc0 + 4];
        float v0 = 4.0f * m.x - u.x - d.x - l   - m.y;
        float v1 = 4.0f * m.y - u.y - d.y - m.x - m.z;
        float v2 = 4.0f * m.z - u.z - d.z - m.y - m.w;
        float v3 = 4.0f * m.w - u.w - d.w - m.z - r;
        acc = fmaf(v0, v0, acc);
        acc = fmaf(v1, v1, acc);
        acc = fmaf(v2, v2, acc);
        acc = fmaf(v3, v3, acc);
    }

    // scalar edges: ox in [0,14] and [3847, 3861]
    if (threadIdx.x < 30) {
        int t = threadIdx.x;
        int ox = (t < 15) ? t : (3832 + t);
        int cl = clampi(ox - 12, 0, IW - 1);
        int cc = clampi(ox - 11, 0, IW - 1);
        int cr = clampi(ox - 10, 0, IW - 1);
        float v = 4.0f * pc[cc] - pu[cc] - pd[cc] - pc[cl] - pc[cr];
        acc = fmaf(v, v, acc);
    }

    __shared__ float sbuf[LAP_THREADS];
    sbuf[threadIdx.x] = acc;
    __syncthreads();
#pragma unroll
    for (int s = LAP_THREADS / 2; s > 0; s >>= 1) {
        if (threadIdx.x < s) sbuf[threadIdx.x] += sbuf[threadIdx.x + s];
        __syncthreads();
    }
    if (threadIdx.x == 0) g_partials[row] = sbuf[0];
}

// ---------------------------------------------------------------------------
// Kernel 3: final deterministic reduction in double -> mean scalar.
// ---------------------------------------------------------------------------
__global__ void __launch_bounds__(256)
reduce_kernel(float* __restrict__ out_scalar)
{
    __shared__ double sd[256];
    double s = 0.0;
    for (int i = threadIdx.x; i < LAP_ROWS; i += 256) s += (double)g_partials[i];
    sd[threadIdx.x] = s;
    __syncthreads();
#pragma unroll
    for (int k = 128; k > 0; k >>= 1) {
        if (threadIdx.x < k) sd[threadIdx.x] += sd[threadIdx.x + k];
        __syncthreads();
    }
    if (threadIdx.x == 0)
        out_scalar[0] = (float)(sd[0] / (double)L3);
}

extern "C" void kernel_launch(void* const* d_in, const int* in_sizes, int n_in,
                              void* d_out, int out_size)
{
    const float* img   = (const float*)d_in[0];  // (1,3,2160,3840)
    const float* noise = (const float*)d_in[1];  // (1,1,2160,3840)
    const float* g     = (const float*)d_in[2];  // (25,25)
    float* out = (float*)d_out;                  // [3*H*W conv output, 1 scalar]

    // Stage duplicated weight pairs, then copy both tables into constant bank.
    dup_kernel<<<(KS * KS + 127) / 128, 128>>>(g);
    cudaMemcpyToSymbolAsync(c_w, g, KS * KS * sizeof(float), 0,
                            cudaMemcpyDeviceToDevice, 0);
    void* w2_ptr = nullptr;
    cudaGetSymbolAddress(&w2_ptr, g_w2_stage);
    cudaMemcpyToSymbolAsync(c_w2, w2_ptr, KS * KS * sizeof(ULL), 0,
                            cudaMemcpyDeviceToDevice, 0);

    dim3 gridB(IW / TILE, (IH + TILE - 1) / TILE);   // 120 x 68
    blur_kernel<<<gridB, BLK_THREADS>>>(img, noise, out);

    lap_kernel<<<LAP_ROWS, LAP_THREADS>>>(img);
    reduce_kernel<<<1, 256>>>(out + (out_size - 1));
}

// round 11
// speedup vs baseline: 1.2082x; 1.0456x over previous
#include <cuda_runtime.h>
#include <cuda_bf16.h>

typedef unsigned long long ULL;

// Problem constants (fixed by setup_inputs)
#define IH 2160
#define IW 3840
#define HW (IH * IW)
#define KS 25
#define PADK 12
#define LH (IH + 22)
#define LW (IW + 22)
#define L3 (3 * LH * LW)

// Blur tiling: 32x32 outputs per block, 128 threads (4 warps x 8 cols, lane = row)
#define TILE 32
#define SROWS 56
#define SCOLS 56
#define SSTRIDE 57          // float2 stride for ch0/1 (odd -> conflict-free LDS.64)
#define S2STRIDE 29         // float2-pair stride for ch2 (29 mod 16 = 13 -> conflict-free)
#define BLK_THREADS 128
#define RING 10             // ch0/1 rotating window slots
#define PRING 8             // ch2 pair-ring slots

// Weights in constant memory:
//   c_w  : scalar weights  -> UR operand for scalar FFMA (ch2)
//   c_w2 : duplicated (w,w) -> UR64 operand for fma.rn.f32x2 (ch0/1)
__constant__ float c_w [KS * KS];
__constant__ ULL   c_w2[KS * KS];
__device__   ULL   g_w2_stage[KS * KS];

// Laplacian
#define LAP_ROWS (3 * LH)            // 6546
#define LAP_THREADS 256
#define LAP_VCHUNKS 958
__device__ float g_partials[LAP_ROWS];

__device__ __forceinline__ int clampi(int v, int lo, int hi) {
    return min(max(v, lo), hi);
}

// ---------------------------------------------------------------------------
// Kernel 0: duplicate weights into (w,w) pairs (staging for c_w2).
// ---------------------------------------------------------------------------
__global__ void dup_kernel(const float* __restrict__ g)
{
    int i = blockIdx.x * blockDim.x + threadIdx.x;
    if (i < KS * KS) {
        float w = g[i];
        float2 p = make_float2(w, w);
        g_w2_stage[i] = *reinterpret_cast<ULL*>(&p);
    }
}

// ---------------------------------------------------------------------------
// Kernel 1: 25x25 depthwise blur, edge-replicate pad, + noise.
// ch0/ch1: f32x2 FFMA with UR64 weight (2 FMAs/slot).
// ch2:     scalar FFMA with UR weight; window data held as float2 PAIRS
//          (one LDS.64 feeds 2 columns) -> total LDS/warp/ky: 64 -> 48,
//          dropping below the 2-cyc LDS issue floor so the fma pipe binds.
// ---------------------------------------------------------------------------
__global__ void __launch_bounds__(BLK_THREADS)
blur_kernel(const float* __restrict__ img,
            const float* __restrict__ noise,
            float* __restrict__ out)
{
    __shared__ float2 s01[SROWS * SSTRIDE];    // channels 0,1 packed
    __shared__ float2 s2p[SROWS * S2STRIDE];   // channel 2, even-column pairs

    const int tx0 = blockIdx.x * TILE;
    const int ty0 = blockIdx.y * TILE;
    const int tid = threadIdx.x;

    // tile load with edge clamp; incremental r,c (no div/mod in loop body)
    {
        int r = tid / SCOLS;
        int c = tid - r * SCOLS;
        float* s2f = reinterpret_cast<float*>(s2p);   // float stride 58
        for (int i = tid; i < SROWS * SCOLS; i += BLK_THREADS) {
            int gy = clampi(ty0 - PADK + r, 0, IH - 1);
            int gx = clampi(tx0 - PADK + c, 0, IW - 1);
            int gi = gy * IW + gx;
            s01[r * SSTRIDE + c] = make_float2(img[gi], img[HW + gi]);
            s2f[r * (2 * S2STRIDE) + c] = img[2 * HW + gi];
            r += 2; c += 16;                          // 128 = 2*56 + 16
            if (c >= SCOLS) { c -= SCOLS; r += 1; }
        }
    }
    __syncthreads();

    const int lane = tid & 31;      // output row within tile
    const int wid  = tid >> 5;      // x-group (0..3)
    const int xb   = wid * 8;       // column base within tile (even)

    ULL   acc01[8];
    float acc2 [8];
#pragma unroll
    for (int j = 0; j < 8; j++) { acc01[j] = 0ull; acc2[j] = 0.0f; }

#pragma unroll 1
    for (int ky = 0; ky < KS; ++ky) {
        const ULL*    rowp = reinterpret_cast<const ULL*>(s01 + (lane + ky) * SSTRIDE + xb);
        const float2* p2   = s2p + (lane + ky) * S2STRIDE + (xb >> 1);
        const int wbase = ky * KS;

        // prime rotating windows
        ULL    a [RING];           // ch0/1 columns xb+0 .. xb+9
        float2 cp[PRING];          // ch2 even pairs 0..5 (cols 0..11)
#pragma unroll
        for (int i = 0; i < RING; i++) a[i] = rowp[i];
#pragma unroll
        for (int i = 0; i < 6; i++) cp[i] = p2[i];

#pragma unroll
        for (int kx = 0; kx < KS; ++kx) {
            const ULL   ww = c_w2[wbase + kx];  // uniform -> UR64
            const float wv = c_w [wbase + kx];  // uniform -> UR
#pragma unroll
            for (int j = 0; j < 8; j++) {
                const int s = (kx + j) % RING;          // compile-time
                asm("fma.rn.f32x2 %0, %1, %2, %0;"
                    : "+l"(acc01[j]) : "l"(a[s]), "l"(ww));
                const int p  = ((kx + j) >> 1) & (PRING - 1);
                const float d2 = ((kx + j) & 1) ? cp[p].y : cp[p].x;
                acc2[j] = fmaf(d2, wv, acc2[j]);
            }
            if (kx < KS - 3)                            // ch0/1 cols 10..31
                a[kx % RING] = rowp[RING + kx];
            if ((kx & 1) == 0 && kx <= 18)              // ch2 pairs 6..15
                cp[(kx / 2 + 6) & (PRING - 1)] = p2[kx / 2 + 6];
        }
    }

    const int y = ty0 + lane;
    if (y < IH) {                               // last block row is half-tall
        const int x = tx0 + xb;
        const int base = y * IW + x;
        float4 n0 = *reinterpret_cast<const float4*>(noise + base);
        float4 n1 = *reinterpret_cast<const float4*>(noise + base + 4);

        float v0[8], v1[8];
#pragma unroll
        for (int j = 0; j < 8; j++) {
            float2 f = *reinterpret_cast<float2*>(&acc01[j]);
            v0[j] = f.x; v1[j] = f.y;
        }
        *reinterpret_cast<float4*>(out + 0 * HW + base) =
            make_float4(v0[0] + n0.x, v0[1] + n0.y, v0[2] + n0.z, v0[3] + n0.w);
        *reinterpret_cast<float4*>(out + 0 * HW + base + 4) =
            make_float4(v0[4] + n1.x, v0[5] + n1.y, v0[6] + n1.z, v0[7] + n1.w);
        *reinterpret_cast<float4*>(out + 1 * HW + base) =
            make_float4(v1[0] + n0.x, v1[1] + n0.y, v1[2] + n0.z, v1[3] + n0.w);
        *reinterpret_cast<float4*>(out + 1 * HW + base + 4) =
            make_float4(v1[4] + n1.x, v1[5] + n1.y, v1[6] + n1.z, v1[7] + n1.w);
        *reinterpret_cast<float4*>(out + 2 * HW + base) =
            make_float4(acc2[0] + n0.x, acc2[1] + n0.y, acc2[2] + n0.z, acc2[3] + n0.w);
        *reinterpret_cast<float4*>(out + 2 * HW + base + 4) =
            make_float4(acc2[4] + n1.x, acc2[5] + n1.y, acc2[6] + n1.z, acc2[7] + n1.w);
    }
}

// ---------------------------------------------------------------------------
// Kernel 2: Laplacian (3x3, pad=12 replicate), squared, per-row partial sums.
// ---------------------------------------------------------------------------
__global__ void __launch_bounds__(LAP_THREADS)
lap_kernel(const float* __restrict__ img)
{
    const int row = blockIdx.x;          // 0 .. LAP_ROWS-1
    const int ch  = row / LH;
    const int oy  = row - ch * LH;
    const float* p = img + ch * HW;

    const int ru = clampi(oy - 12, 0, IH - 1);
    const int rc = clampi(oy - 11, 0, IH - 1);
    const int rd = clampi(oy - 10, 0, IH - 1);
    const float* __restrict__ pu = p + ru * IW;
    const float* __restrict__ pc = p + rc * IW;
    const float* __restrict__ pd = p + rd * IW;

    float acc = 0.0f;

    // vector interior: cc0 = 4 + 4c (16B aligned)
    for (int c = threadIdx.x; c < LAP_VCHUNKS; c += LAP_THREADS) {
        int cc0 = 4 + 4 * c;
        float4 u = *reinterpret_cast<const float4*>(pu + cc0);
        float4 m = *reinterpret_cast<const float4*>(pc + cc0);
        float4 d = *reinterpret_cast<const float4*>(pd + cc0);
        float l = pc[cc0 - 1];
        float r = pc[cc0 + 4];
        float v0 = 4.0f * m.x - u.x - d.x - l   - m.y;
        float v1 = 4.0f * m.y - u.y - d.y - m.x - m.z;
        float v2 = 4.0f * m.z - u.z - d.z - m.y - m.w;
        float v3 = 4.0f * m.w - u.w - d.w - m.z - r;
        acc = fmaf(v0, v0, acc);
        acc = fmaf(v1, v1, acc);
        acc = fmaf(v2, v2, acc);
        acc = fmaf(v3, v3, acc);
    }

    // scalar edges: ox in [0,14] and [3847, 3861]
    if (threadIdx.x < 30) {
        int t = threadIdx.x;
        int ox = (t < 15) ? t : (3832 + t);
        int cl = clampi(ox - 12, 0, IW - 1);
        int cc = clampi(ox - 11, 0, IW - 1);
        int cr = clampi(ox - 10, 0, IW - 1);
        float v = 4.0f * pc[cc] - pu[cc] - pd[cc] - pc[cl] - pc[cr];
        acc = fmaf(v, v, acc);
    }

    __shared__ float sbuf[LAP_THREADS];
    sbuf[threadIdx.x] = acc;
    __syncthreads();
#pragma unroll
    for (int s = LAP_THREADS / 2; s > 0; s >>= 1) {
        if (threadIdx.x < s) sbuf[threadIdx.x] += sbuf[threadIdx.x + s];
        __syncthreads();
    }
    if (threadIdx.x == 0) g_partials[row] = sbuf[0];
}

// ---------------------------------------------------------------------------
// Kernel 3: final deterministic reduction in double -> mean scalar.
// 4 interleaved accumulators break the dependent-add chain.
// ---------------------------------------------------------------------------
__global__ void __launch_bounds__(256)
reduce_kernel(float* __restrict__ out_scalar)
{
    __shared__ double sd[256];
    double s0 = 0.0, s1 = 0.0, s2 = 0.0, s3 = 0.0;
    for (int i = threadIdx.x; i < LAP_ROWS; i += 1024) {
        if (i           < LAP_ROWS) s0 += (double)g_partials[i];
        if (i + 256     < LAP_ROWS) s1 += (double)g_partials[i + 256];
        if (i + 512     < LAP_ROWS) s2 += (double)g_partials[i + 512];
        if (i + 768     < LAP_ROWS) s3 += (double)g_partials[i + 768];
    }
    sd[threadIdx.x] = (s0 + s1) + (s2 + s3);
    __syncthreads();
#pragma unroll
    for (int k = 128; k > 0; k >>= 1) {
        if (threadIdx.x < k) sd[threadIdx.x] += sd[threadIdx.x + k];
        __syncthreads();
    }
    if (threadIdx.x == 0)
        out_scalar[0] = (float)(sd[0] / (double)L3);
}

extern "C" void kernel_launch(void* const* d_in, const int* in_sizes, int n_in,
                              void* d_out, int out_size)
{
    const float* img   = (const float*)d_in[0];  // (1,3,2160,3840)
    const float* noise = (const float*)d_in[1];  // (1,1,2160,3840)
    const float* g     = (const float*)d_in[2];  // (25,25)
    float* out = (float*)d_out;                  // [3*H*W conv output, 1 scalar]

    // Stage duplicated weight pairs, then copy both tables into constant bank.
    dup_kernel<<<(KS * KS + 127) / 128, 128>>>(g);
    cudaMemcpyToSymbolAsync(c_w, g, KS * KS * sizeof(float), 0,
                            cudaMemcpyDeviceToDevice, 0);
    void* w2_ptr = nullptr;
    cudaGetSymbolAddress(&w2_ptr, g_w2_stage);
    cudaMemcpyToSymbolAsync(c_w2, w2_ptr, KS * KS * sizeof(ULL), 0,
                            cudaMemcpyDeviceToDevice, 0);

    dim3 gridB(IW / TILE, (IH + TILE - 1) / TILE);   // 120 x 68
    blur_kernel<<<gridB, BLK_THREADS>>>(img, noise, out);

    lap_kernel<<<LAP_ROWS, LAP_THREADS>>>(img);
    reduce_kernel<<<1, 256>>>(out + (out_size - 1));
}